// round 12
// baseline (speedup 1.0000x reference)
#include <cuda_runtime.h>
#include <cuda_bf16.h>

#define NN 4096
#define MM 512
#define DD 32
#define NBLK 256        // 16 rows per block
#define NT   512        // 16 warps; warp w owns m in [32w, 32w+32)

typedef unsigned long long ull;

// sm_103a packed fp32 FMA (FFMA2). Element 0 = low 32 bits.
__device__ __forceinline__ ull ffma2(ull a, ull b, ull c) {
    ull d;
    asm("fma.rn.f32x2 %0, %1, %2, %3;" : "=l"(d) : "l"(a), "l"(b), "l"(c));
    return d;
}
__device__ __forceinline__ float flo(ull v) { return __uint_as_float((unsigned)v); }
__device__ __forceinline__ float fhi(ull v) { return __uint_as_float((unsigned)(v >> 32)); }
__device__ __forceinline__ float sqrt_approx(float v) {
    float r;
    asm("sqrt.approx.f32 %0, %1;" : "=f"(r) : "f"(v));
    return r;
}
__device__ __forceinline__ float ex2_approx(float v) {
    float r;
    asm("ex2.approx.f32 %0, %1;" : "=f"(r) : "f"(v));
    return r;
}
__device__ __forceinline__ void cp_async16(unsigned dst, const void* src) {
    asm volatile("cp.async.cg.shared.global [%0], [%1], 16;" :: "r"(dst), "l"(src) : "memory");
}

// ---- smem layout (floats) --------------------------------------------------
// y warp slice: 4 tiles x (8 m x 32 d = 256 floats) with stride 260 (skew so
// the two halves' concurrent tile reads are 8 banks apart) -> 1040 f/warp.
#define RS_OFF    0                       // r [16][516] padded           8256
#define XS_OFF    8256                    // x [16][36] padded             576
#define YSW_OFF   (XS_OFF + 576)          // y [16 warps][1040]          16640
#define YN2W_OFF  (YSW_OFF + 16640)       // |y|^2 [16 warps][32]          512
#define XN2_OFF   (YN2W_OFF + 512)        // |x|^2 [16]                     16
#define PART_OFF  (XN2_OFF + 16)          // partials [3][16][16]          768
#define SMEM_FLOATS (PART_OFF + 768)
#define SMEM_BYTES  (SMEM_FLOATS * 4)     // ~107 KB -> 2 blocks/SM

// ---------------------------------------------------------------------------
// 16 Sinkhorn rows per block, 256 blocks -> TWO independent blocks per SM
// (the point of this round: desynchronized blocks fill each other's stalls).
//  row = lane&15, half = lane>>4; warp w owns m[32w,32w+32), half h the
//  16 m at 32w+16h as 2 tiles of 8.
//  r: cp.async.cg coalesced, waited between dots and epilogue.
//  y: warp-local staging (32 rows, skewed tiles); x: block-staged; 1 barrier.
//  dots: d-packed f32x2 FFMAs; y broadcast (2 addrs/instr, conflict-free).
//  C = sqrt(|x|^2+|y|^2-2dot); K = ex2(-C*log2e/2); 16-row local early stop.
// ---------------------------------------------------------------------------
__global__ __launch_bounds__(NT, 2) void sinkhorn_fused_kernel(
    const float* __restrict__ x,   // [NN, DD]
    const float* __restrict__ y,   // [MM, DD]
    const float* __restrict__ r,   // [NN, MM]
    float* __restrict__ out)       // [NN]
{
    extern __shared__ float sm[];
    float4* rs4  = (float4*)(sm + RS_OFF);    // [16][129] float4
    float4* xs4  = (float4*)(sm + XS_OFF);    // [16][9]  float4
    float*  ysw  = sm + YSW_OFF;
    float*  yn2w = sm + YN2W_OFF;
    float*  xn2s = sm + XN2_OFF;
    float*  part = sm + PART_OFF;

    const int tid  = threadIdx.x;
    const int warp = tid >> 5;
    const int lane = tid & 31;
    const int row  = lane & 15;
    const int half = lane >> 4;
    const int nb   = blockIdx.x << 4;

    // ---- r: cp.async.cg, coalesced ----------------------------------------
    {
        const float4*  rg4 = (const float4*)r;
        const unsigned rs_base = (unsigned)__cvta_generic_to_shared(rs4);
#pragma unroll
        for (int k = 0; k < 4; k++) {
            int idx = tid + 512 * k;                 // 0..2047
            int rr = idx >> 7, c4 = idx & 127;
            cp_async16(rs_base + (unsigned)(rr * 129 + c4) * 16u,
                       rg4 + (size_t)(nb + rr) * 128 + c4);
        }
        asm volatile("cp.async.commit_group;" ::: "memory");
    }

    // ---- y: warp-local staging of 32 y-rows into skewed tile layout --------
    {
        const float4* ygw = (const float4*)(y + (size_t)(warp << 5) * DD); // 256 f4
        float*        slice = ysw + warp * 1040;
#pragma unroll
        for (int k = 0; k < 8; k++) {
            int q    = lane + 32 * k;                // f4 index 0..255
            int mu   = q >> 3;                       // local m 0..31
            int slot = q & 7;                        // d-quad
            float4 a = ygw[q];
            *(float4*)(slice + (mu >> 3) * 260 + (mu & 7) * 32 + slot * 4) = a;
            float sq = fmaf(a.x, a.x, fmaf(a.y, a.y, fmaf(a.z, a.z, a.w * a.w)));
            sq += __shfl_xor_sync(0xffffffffu, sq, 1);
            sq += __shfl_xor_sync(0xffffffffu, sq, 2);
            sq += __shfl_xor_sync(0xffffffffu, sq, 4);
            if ((lane & 7) == 0) yn2w[warp * 32 + (lane >> 3) + 4 * k] = sq;
        }
    }

    // ---- x staging (tid<128): padded copy + |x|^2 via 8-lane shfl ----------
    if (tid < 128) {
        int m = tid >> 3, slot = tid & 7;
        float4 a = ((const float4*)x)[(nb + m) * 8 + slot];
        xs4[m * 9 + slot] = a;
        float sq = fmaf(a.x, a.x, fmaf(a.y, a.y, fmaf(a.z, a.z, a.w * a.w)));
        sq += __shfl_xor_sync(0xffffffffu, sq, 1);
        sq += __shfl_xor_sync(0xffffffffu, sq, 2);
        sq += __shfl_xor_sync(0xffffffffu, sq, 4);
        if (slot == 0) xn2s[m] = sq;
    }
    __syncthreads();   // x, xn2 visible; y was warp-local (covered implicitly)

    // ---- dots for this thread's 2 tiles (tiles 2*half, 2*half+1) -----------
    const ulonglong2* xs2   = (const ulonglong2*)xs4;             // [16][9]
    const float*      slice = ysw + warp * 1040;
    float dots0[8];
    ull   A[8];

#pragma unroll
    for (int tp = 0; tp < 2; tp++) {
        const float* tbase = slice + (2 * half + tp) * 260;
#pragma unroll
        for (int j = 0; j < 8; j++) A[j] = 0;
#pragma unroll
        for (int p2 = 0; p2 < 8; p2++) {             // 4 d's per step
            ulonglong2 xp = xs2[row * 9 + p2];       // 2-lane multicast
#pragma unroll
            for (int j = 0; j < 8; j++) {
                ulonglong2 yp = *(const ulonglong2*)(tbase + j * 32 + p2 * 4);
                A[j] = ffma2(xp.x, yp.x, A[j]);
                A[j] = ffma2(xp.y, yp.y, A[j]);
            }
        }
        if (tp == 0) {
#pragma unroll
            for (int j = 0; j < 8; j++) dots0[j] = flo(A[j]) + fhi(A[j]);
        }
    }

    // ---- r has had the whole dot phase to land -----------------------------
    asm volatile("cp.async.wait_group 0;" ::: "memory");
    __syncthreads();

    // ---- epilogue: 16 m per thread (2 tiles) -------------------------------
    const float xn2 = xn2s[row];
    const int   mq  = (warp << 3) + (half << 2);     // f4 col of m-chunk start
    float Racc = 0.f, Sacc = 0.f, Tacc = 0.f;
#pragma unroll
    for (int tp = 0; tp < 2; tp++) {
        const int tl = 2 * half + tp;                // tile 0..3 in warp chunk
        float4 r4a = rs4[row * 129 + mq + 2 * tp];
        float4 r4b = rs4[row * 129 + mq + 2 * tp + 1];
        float rv[8] = { r4a.x, r4a.y, r4a.z, r4a.w, r4b.x, r4b.y, r4b.z, r4b.w };
#pragma unroll
        for (int j = 0; j < 8; j++) {
            float dot = tp ? (flo(A[j]) + fhi(A[j])) : dots0[j];
            float d2  = fmaf(-2.f, dot, xn2 + yn2w[warp * 32 + tl * 8 + j]);
            float C   = sqrt_approx(fmaxf(d2, 0.f));
            float K   = ex2_approx(C * -0.72134752f);   // exp(-C/2)
            Racc += K;
            float Kr = K * rv[j];
            Sacc += Kr;
            Tacc = fmaf(Kr, C, Tacc);
        }
    }

    // ---- fold the two halves (same row), then cross-warp via smem ----------
    Racc += __shfl_down_sync(0xffffffffu, Racc, 16);
    Sacc += __shfl_down_sync(0xffffffffu, Sacc, 16);
    Tacc += __shfl_down_sync(0xffffffffu, Tacc, 16);
    if (lane < 16) {
        part[(0 * 16 + warp) * 16 + row] = Racc;
        part[(1 * 16 + warp) * 16 + row] = Sacc;
        part[(2 * 16 + warp) * 16 + row] = Tacc;
    }
    __syncthreads();

    if (warp == 0) {
        float R = 1.f, S = 1.f, T = 0.f;
        if (lane < 16) {
            R = 0.f; S = 0.f; T = 0.f;
#pragma unroll
            for (int w = 0; w < 16; w++) {
                R += part[(0 * 16 + w) * 16 + lane];
                S += part[(1 * 16 + w) * 16 + lane];
                T += part[(2 * 16 + w) * 16 + lane];
            }
        }

        // Scalar Sinkhorn recurrence, 16-row local early stop:
        //   iter 1:   u = 1/(R + 1e-8)
        //   iter t>1: u = 1/(S/(u+1e-8) + 1e-8)
        //   stop once mean_16 |u_new - u| < 0.1 (after applying update)
        float u = 1.f;
        bool done = false;
        for (int t = 0; t < 100 && !done; t++) {
            float denom = (t == 0) ? R : (S / (u + 1e-8f));
            float un = 1.f / (denom + 1e-8f);
            float e = (lane < 16) ? fabsf(un - u) : 0.f;
            u = un;
#pragma unroll
            for (int off = 16; off > 0; off >>= 1)
                e += __shfl_xor_sync(0xffffffffu, e, off);
            done = (e < 0.1f * 16.f);        // uniform across warp
        }
        if (lane < 16) out[nb + lane] = u * T / (u + 1e-8f);
    }
}

extern "C" void kernel_launch(void* const* d_in, const int* in_sizes, int n_in,
                              void* d_out, int out_size)
{
    const float* x = (const float*)d_in[0];  // [4096, 32]
    const float* y = (const float*)d_in[1];  // [512, 32]
    const float* r = (const float*)d_in[2];  // [4096, 512]
    float* out = (float*)d_out;              // [4096]

    cudaFuncSetAttribute(sinkhorn_fused_kernel,
                         cudaFuncAttributeMaxDynamicSharedMemorySize, SMEM_BYTES);
    sinkhorn_fused_kernel<<<NBLK, NT, SMEM_BYTES>>>(x, y, r, out);
}

// round 13
// speedup vs baseline: 1.3692x; 1.3692x over previous
#include <cuda_runtime.h>
#include <cuda_bf16.h>

#define NN 4096
#define MM 512
#define DD 32
#define NBLK 128        // 32 rows per block
#define NT   512        // 16 warps: (wr 0..1) x (wc 0..7); warp tile 16n x 64m

// ---- smem layout (float offsets) -------------------------------------------
#define RS_OFF   0                        // r f32 [32][516] padded      16512
#define YBH_OFF  16512                    // y bf16-hi pairs [512][20]   10240
#define YBL_OFF  (YBH_OFF + 10240)        // y bf16-lo pairs [512][20]   10240
#define XBH_OFF  (YBL_OFF + 10240)        // x bf16-hi pairs [32][20]      640
#define XBL_OFF  (XBH_OFF + 640)          // x bf16-lo pairs [32][20]      640
#define YN2_OFF  (XBL_OFF + 640)          // |y|^2 f32 [512]               512
#define XN2_OFF  (YN2_OFF + 512)          // |x|^2 f32 [32]                 32
#define PART_OFF (XN2_OFF + 32)           // partials [3][8][32]           768
#define SMEM_FLOATS (PART_OFF + 768)
#define SMEM_BYTES  (SMEM_FLOATS * 4)     // 158336 B -> 1 block/SM

__device__ __forceinline__ float sqrt_approx(float v) {
    float r; asm("sqrt.approx.f32 %0, %1;" : "=r"(*(unsigned*)&r) : "f"(v)); return r;
}
__device__ __forceinline__ float ex2_approx(float v) {
    float r; asm("ex2.approx.f32 %0, %1;" : "=f"(r) : "f"(v)); return r;
}
__device__ __forceinline__ void cp_async16(unsigned dst, const void* src) {
    asm volatile("cp.async.cg.shared.global [%0], [%1], 16;" :: "r"(dst), "l"(src) : "memory");
}
// pack two floats into bf16x2: low 16 bits = lo, high = hi
__device__ __forceinline__ unsigned pack_bf16(float lo, float hi) {
    unsigned r;
    asm("cvt.rn.bf16x2.f32 %0, %1, %2;" : "=r"(r) : "f"(hi), "f"(lo));
    return r;
}
__device__ __forceinline__ float bf_lo_f32(unsigned w) { return __uint_as_float(w << 16); }
__device__ __forceinline__ float bf_hi_f32(unsigned w) { return __uint_as_float(w & 0xffff0000u); }

__device__ __forceinline__ void mma_bf16(float& c0, float& c1, float& c2, float& c3,
                                         unsigned a0, unsigned a1, unsigned a2, unsigned a3,
                                         unsigned b0, unsigned b1) {
    asm("mma.sync.aligned.m16n8k16.row.col.f32.bf16.bf16.f32 "
        "{%0,%1,%2,%3}, {%4,%5,%6,%7}, {%8,%9}, {%0,%1,%2,%3};"
        : "+f"(c0), "+f"(c1), "+f"(c2), "+f"(c3)
        : "r"(a0), "r"(a1), "r"(a2), "r"(a3), "r"(b0), "r"(b1));
}

// ---------------------------------------------------------------------------
// Tensor-core Sinkhorn. 32 rows/block. dot[n][m] via bf16x3-split mma.sync
// (xh*yh + xl*yh + xh*yl, fp32 accum); norms in fp32; C=sqrt(|x|^2+|y|^2-2dot);
// K=exp(-C/2); R=sum K, S=sum K*r, T=sum K*C*r; block-local early-stopped
// scalar u-recurrence; out[n] = u*T/(u+1e-8).
// Fragment mapping (g=lane>>2, t=lane&3), m16n8k16 row.col:
//  A: a0={x[g][2t..+1]}, a1=row g+8, a2=k+8, a3=both  -> words t(,+4)+8ks
//  B: b0={y[mb+g][2t..+1]}, b1=k+8                    -> words t(,+4)+8ks
//  D: c0=D[g][2t], c1=[g][2t+1], c2=[g+8][2t], c3=[g+8][2t+1]
// B smem stride 20 words -> (g*20+t) mod 32 covers all banks: conflict-free.
// ---------------------------------------------------------------------------
__global__ __launch_bounds__(NT, 1) void sinkhorn_tc_kernel(
    const float* __restrict__ x,   // [NN, DD]
    const float* __restrict__ y,   // [MM, DD]
    const float* __restrict__ r,   // [NN, MM]
    float* __restrict__ out)       // [NN]
{
    extern __shared__ float sm[];
    float4*   rs4  = (float4*)(sm + RS_OFF);     // [32][129] float4
    unsigned* ybh  = (unsigned*)(sm + YBH_OFF);  // [512][20]
    unsigned* ybl  = (unsigned*)(sm + YBL_OFF);
    unsigned* xbh  = (unsigned*)(sm + XBH_OFF);  // [32][20]
    unsigned* xbl  = (unsigned*)(sm + XBL_OFF);
    float*    yn2  = sm + YN2_OFF;
    float*    xn2s = sm + XN2_OFF;
    float*    part = sm + PART_OFF;

    const int tid  = threadIdx.x;
    const int warp = tid >> 5;
    const int lane = tid & 31;
    const int g    = lane >> 2;
    const int t    = lane & 3;
    const int wr   = warp >> 3;          // 0..1 : 16-row group
    const int wc   = warp & 7;           // 0..7 : 64-m chunk
    const int nb   = blockIdx.x << 5;
    const int mchunk = wc << 6;

    // ---- r: cp.async.cg coalesced into padded [32][516] --------------------
    {
        const float4*  rg4 = (const float4*)r;
        const unsigned rs_base = (unsigned)__cvta_generic_to_shared(rs4);
#pragma unroll
        for (int k = 0; k < 8; k++) {
            int idx = tid + 512 * k;             // 0..4095
            int row = idx >> 7, c4 = idx & 127;
            cp_async16(rs_base + (unsigned)(row * 129 + c4) * 16u,
                       rg4 + (size_t)(nb + row) * 128 + c4);
        }
        asm volatile("cp.async.commit_group;" ::: "memory");
    }

    // ---- y: f32 load -> bf16 hi/lo split tables + |y|^2 --------------------
    const float4* yg4 = (const float4*)y;        // 4096 float4
#pragma unroll
    for (int k = 0; k < 8; k++) {
        int idx  = tid + 512 * k;
        float4 a = yg4[idx];
        int m = idx >> 3, q = idx & 7;           // q = f4 slot -> pair words 2q,2q+1
        unsigned h0 = pack_bf16(a.x, a.y), h1 = pack_bf16(a.z, a.w);
        unsigned l0 = pack_bf16(a.x - bf_lo_f32(h0), a.y - bf_hi_f32(h0));
        unsigned l1 = pack_bf16(a.z - bf_lo_f32(h1), a.w - bf_hi_f32(h1));
        ybh[m * 20 + 2 * q]     = h0;  ybh[m * 20 + 2 * q + 1] = h1;
        ybl[m * 20 + 2 * q]     = l0;  ybl[m * 20 + 2 * q + 1] = l1;
        float sq = fmaf(a.x, a.x, fmaf(a.y, a.y, fmaf(a.z, a.z, a.w * a.w)));
        sq += __shfl_xor_sync(0xffffffffu, sq, 1);
        sq += __shfl_xor_sync(0xffffffffu, sq, 2);
        sq += __shfl_xor_sync(0xffffffffu, sq, 4);
        if (q == 0) yn2[m] = sq;
    }

    // ---- x: same split for the block's 32 rows + |x|^2 ---------------------
    if (tid < 256) {
        int m = tid >> 3, q = tid & 7;
        float4 a = ((const float4*)x)[(nb + m) * 8 + q];
        unsigned h0 = pack_bf16(a.x, a.y), h1 = pack_bf16(a.z, a.w);
        unsigned l0 = pack_bf16(a.x - bf_lo_f32(h0), a.y - bf_hi_f32(h0));
        unsigned l1 = pack_bf16(a.z - bf_lo_f32(h1), a.w - bf_hi_f32(h1));
        xbh[m * 20 + 2 * q]     = h0;  xbh[m * 20 + 2 * q + 1] = h1;
        xbl[m * 20 + 2 * q]     = l0;  xbl[m * 20 + 2 * q + 1] = l1;
        float sq = fmaf(a.x, a.x, fmaf(a.y, a.y, fmaf(a.z, a.z, a.w * a.w)));
        sq += __shfl_xor_sync(0xffffffffu, sq, 1);
        sq += __shfl_xor_sync(0xffffffffu, sq, 2);
        sq += __shfl_xor_sync(0xffffffffu, sq, 4);
        if (q == 0) xn2s[m] = sq;
    }
    __syncthreads();   // y/x tables + norms visible (r still in flight)

    // ---- A fragments: this warp's 16 x-rows, both k-steps, hi and lo -------
    const int la0 = (wr << 4) + g;               // local rows g, g+8 of tile
    const int la1 = la0 + 8;
    unsigned ah[2][4], al[2][4];
#pragma unroll
    for (int ks = 0; ks < 2; ks++) {
        int w0 = t + 8 * ks, w4 = t + 4 + 8 * ks;
        ah[ks][0] = xbh[la0 * 20 + w0];  ah[ks][1] = xbh[la1 * 20 + w0];
        ah[ks][2] = xbh[la0 * 20 + w4];  ah[ks][3] = xbh[la1 * 20 + w4];
        al[ks][0] = xbl[la0 * 20 + w0];  al[ks][1] = xbl[la1 * 20 + w0];
        al[ks][2] = xbl[la0 * 20 + w4];  al[ks][3] = xbl[la1 * 20 + w4];
    }

    // ---- mainloop: 8 n-fragments x 2 k-steps x 3 split terms ---------------
    float acc[8][4];
#pragma unroll
    for (int f = 0; f < 8; f++)
        acc[f][0] = acc[f][1] = acc[f][2] = acc[f][3] = 0.f;

#pragma unroll
    for (int f = 0; f < 8; f++) {
        const int mb = mchunk + 8 * f + g;       // y row this lane feeds
#pragma unroll
        for (int ks = 0; ks < 2; ks++) {
            int w0 = t + 8 * ks, w4 = t + 4 + 8 * ks;
            unsigned bh0 = ybh[mb * 20 + w0], bh1 = ybh[mb * 20 + w4];
            unsigned bl0 = ybl[mb * 20 + w0], bl1 = ybl[mb * 20 + w4];
            mma_bf16(acc[f][0], acc[f][1], acc[f][2], acc[f][3],
                     ah[ks][0], ah[ks][1], ah[ks][2], ah[ks][3], bh0, bh1);
            mma_bf16(acc[f][0], acc[f][1], acc[f][2], acc[f][3],
                     al[ks][0], al[ks][1], al[ks][2], al[ks][3], bh0, bh1);
            mma_bf16(acc[f][0], acc[f][1], acc[f][2], acc[f][3],
                     ah[ks][0], ah[ks][1], ah[ks][2], ah[ks][3], bl0, bl1);
        }
    }

    // ---- r landed under the whole MMA phase --------------------------------
    asm volatile("cp.async.wait_group 0;" ::: "memory");
    __syncthreads();

    // ---- epilogue: rows la0, la1; m-cols mchunk+8f+2t, +1 ------------------
    const float xnA = xn2s[la0], xnB = xn2s[la1];
    float R0 = 0.f, S0 = 0.f, T0 = 0.f, R1 = 0.f, S1 = 0.f, T1 = 0.f;
#pragma unroll
    for (int f = 0; f < 8; f++) {
        const int m0 = mchunk + 8 * f + 2 * t;
        float2 yn = *(const float2*)(yn2 + m0);
        float2 rA = *(const float2*)(sm + RS_OFF + la0 * 516 + m0);
        float2 rB = *(const float2*)(sm + RS_OFF + la1 * 516 + m0);

        float d2, C, K;
        d2 = fmaf(-2.f, acc[f][0], xnA + yn.x);
        C  = sqrt_approx(fmaxf(d2, 0.f)); K = ex2_approx(C * -0.72134752f);
        R0 += K; S0 = fmaf(K, rA.x, S0); T0 = fmaf(K * rA.x, C, T0);

        d2 = fmaf(-2.f, acc[f][1], xnA + yn.y);
        C  = sqrt_approx(fmaxf(d2, 0.f)); K = ex2_approx(C * -0.72134752f);
        R0 += K; S0 = fmaf(K, rA.y, S0); T0 = fmaf(K * rA.y, C, T0);

        d2 = fmaf(-2.f, acc[f][2], xnB + yn.x);
        C  = sqrt_approx(fmaxf(d2, 0.f)); K = ex2_approx(C * -0.72134752f);
        R1 += K; S1 = fmaf(K, rB.x, S1); T1 = fmaf(K * rB.x, C, T1);

        d2 = fmaf(-2.f, acc[f][3], xnB + yn.y);
        C  = sqrt_approx(fmaxf(d2, 0.f)); K = ex2_approx(C * -0.72134752f);
        R1 += K; S1 = fmaf(K, rB.y, S1); T1 = fmaf(K * rB.y, C, T1);
    }

    // reduce across the 4 t-lanes of each g-group
#pragma unroll
    for (int off = 1; off <= 2; off <<= 1) {
        R0 += __shfl_xor_sync(0xffffffffu, R0, off);
        S0 += __shfl_xor_sync(0xffffffffu, S0, off);
        T0 += __shfl_xor_sync(0xffffffffu, T0, off);
        R1 += __shfl_xor_sync(0xffffffffu, R1, off);
        S1 += __shfl_xor_sync(0xffffffffu, S1, off);
        T1 += __shfl_xor_sync(0xffffffffu, T1, off);
    }
    if (t == 0) {
        part[0 * 256 + wc * 32 + la0] = R0;
        part[1 * 256 + wc * 32 + la0] = S0;
        part[2 * 256 + wc * 32 + la0] = T0;
        part[0 * 256 + wc * 32 + la1] = R1;
        part[1 * 256 + wc * 32 + la1] = S1;
        part[2 * 256 + wc * 32 + la1] = T1;
    }
    __syncthreads();

    if (warp == 0) {
        float R = 0.f, S = 0.f, T = 0.f;
#pragma unroll
        for (int w = 0; w < 8; w++) {
            R += part[0 * 256 + w * 32 + lane];
            S += part[1 * 256 + w * 32 + lane];
            T += part[2 * 256 + w * 32 + lane];
        }

        // Scalar Sinkhorn recurrence, block-local early stop:
        //   iter 1:   u = 1/(R + 1e-8)
        //   iter t>1: u = 1/(S/(u+1e-8) + 1e-8)
        //   stop once mean_32 |u_new - u| < 0.1 (after applying update)
        float u = 1.f;
        bool done = false;
        for (int it = 0; it < 100 && !done; it++) {
            float denom = (it == 0) ? R : (S / (u + 1e-8f));
            float un = 1.f / (denom + 1e-8f);
            float e = fabsf(un - u);
            u = un;
#pragma unroll
            for (int off = 16; off > 0; off >>= 1)
                e += __shfl_xor_sync(0xffffffffu, e, off);
            done = (e < 0.1f * 32.f);            // uniform across warp
        }
        out[nb + lane] = u * T / (u + 1e-8f);
    }
}

extern "C" void kernel_launch(void* const* d_in, const int* in_sizes, int n_in,
                              void* d_out, int out_size)
{
    const float* x = (const float*)d_in[0];  // [4096, 32]
    const float* y = (const float*)d_in[1];  // [512, 32]
    const float* r = (const float*)d_in[2];  // [4096, 512]
    float* out = (float*)d_out;              // [4096]

    cudaFuncSetAttribute(sinkhorn_tc_kernel,
                         cudaFuncAttributeMaxDynamicSharedMemorySize, SMEM_BYTES);
    sinkhorn_tc_kernel<<<NBLK, NT, SMEM_BYTES>>>(x, y, r, out);
}

// round 14
// speedup vs baseline: 1.3732x; 1.0029x over previous
#include <cuda_runtime.h>
#include <cuda_bf16.h>

#define NN 4096
#define MM 512
#define DD 32
#define NBLK 128        // 32 rows per block
#define NT   1024       // 32 warps: (wr 0..1) x (wc 0..15); warp tile 16n x 32m

// ---- smem layout (float offsets) -------------------------------------------
#define RS_OFF   0                        // r f32 [32][516] padded      16512
#define YBH_OFF  16512                    // y bf16-hi pairs [512][20]   10240
#define XBH_OFF  (YBH_OFF + 10240)       // x bf16-hi pairs [32][20]       640
#define XBL_OFF  (XBH_OFF + 640)         // x bf16-lo pairs [32][20]       640
#define YN2_OFF  (XBL_OFF + 640)         // |y|^2 f32 [512]                512
#define XN2_OFF  (YN2_OFF + 512)         // |x|^2 f32 [32]                  32
#define PART_OFF (XN2_OFF + 32)          // partials [3][16][32]          1536
#define SMEM_FLOATS (PART_OFF + 1536)
#define SMEM_BYTES  (SMEM_FLOATS * 4)    // ~120 KB -> 1 block/SM

__device__ __forceinline__ float sqrt_approx(float v) {
    float r; asm("sqrt.approx.f32 %0, %1;" : "=f"(r) : "f"(v)); return r;
}
__device__ __forceinline__ float ex2_approx(float v) {
    float r; asm("ex2.approx.f32 %0, %1;" : "=f"(r) : "f"(v)); return r;
}
__device__ __forceinline__ void cp_async16(unsigned dst, const void* src) {
    asm volatile("cp.async.cg.shared.global [%0], [%1], 16;" :: "r"(dst), "l"(src) : "memory");
}
// pack two floats into bf16x2: low 16 bits = lo arg, high = hi arg
__device__ __forceinline__ unsigned pack_bf16(float lo, float hi) {
    unsigned r;
    asm("cvt.rn.bf16x2.f32 %0, %1, %2;" : "=r"(r) : "f"(hi), "f"(lo));
    return r;
}
__device__ __forceinline__ float bf_lo_f32(unsigned w) { return __uint_as_float(w << 16); }
__device__ __forceinline__ float bf_hi_f32(unsigned w) { return __uint_as_float(w & 0xffff0000u); }

__device__ __forceinline__ void mma_bf16(float& c0, float& c1, float& c2, float& c3,
                                         unsigned a0, unsigned a1, unsigned a2, unsigned a3,
                                         unsigned b0, unsigned b1) {
    asm("mma.sync.aligned.m16n8k16.row.col.f32.bf16.bf16.f32 "
        "{%0,%1,%2,%3}, {%4,%5,%6,%7}, {%8,%9}, {%0,%1,%2,%3};"
        : "+f"(c0), "+f"(c1), "+f"(c2), "+f"(c3)
        : "r"(a0), "r"(a1), "r"(a2), "r"(a3), "r"(b0), "r"(b1));
}

// ---------------------------------------------------------------------------
// Tensor-core Sinkhorn, 32 rows/block, 32 warps. dot[n][m] via bf16 2-term
// split (xh*yh + xl*yh, fp32 accum; dropped x*y_lo term ~4e-3 abs on dot ->
// ~1e-5..1e-4 output rel err, tolerance 1e-3). Norms fp32.
// C = sqrt(|x|^2+|y|^2-2dot); K = exp(-C/2); R=sum K, S=sum K*r, T=sum K*C*r;
// block-local early-stopped scalar u-recurrence; out[n] = u*T/(u+1e-8).
// Fragment mapping (g=lane>>2, t=lane&3), m16n8k16 row.col:
//  A: a0={x[g][2t..+1]}, a1=row g+8, a2=k+8, a3=both  -> words t(,+4)+8ks
//  B: b0={y[mb+g][2t..+1]}, b1=k+8                    -> words t(,+4)+8ks
//  D: c0=D[g][2t], c1=[g][2t+1], c2=[g+8][2t], c3=[g+8][2t+1]
// B stride 20 words -> (g*20+t) mod 32 covers all 32 banks: conflict-free.
// ---------------------------------------------------------------------------
__global__ __launch_bounds__(NT, 1) void sinkhorn_tc_kernel(
    const float* __restrict__ x,   // [NN, DD]
    const float* __restrict__ y,   // [MM, DD]
    const float* __restrict__ r,   // [NN, MM]
    float* __restrict__ out)       // [NN]
{
    extern __shared__ float sm[];
    float4*   rs4  = (float4*)(sm + RS_OFF);     // [32][129] float4
    unsigned* ybh  = (unsigned*)(sm + YBH_OFF);  // [512][20]
    unsigned* xbh  = (unsigned*)(sm + XBH_OFF);  // [32][20]
    unsigned* xbl  = (unsigned*)(sm + XBL_OFF);
    float*    yn2  = sm + YN2_OFF;
    float*    xn2s = sm + XN2_OFF;
    float*    part = sm + PART_OFF;

    const int tid  = threadIdx.x;
    const int warp = tid >> 5;
    const int lane = tid & 31;
    const int g    = lane >> 2;
    const int t    = lane & 3;
    const int wr   = warp >> 4;          // 0..1  : 16-row group
    const int wc   = warp & 15;          // 0..15 : 32-m chunk
    const int nb   = blockIdx.x << 5;
    const int mchunk = wc << 5;

    // ---- r: cp.async.cg coalesced into padded [32][516] --------------------
    {
        const float4*  rg4 = (const float4*)r;
        const unsigned rs_base = (unsigned)__cvta_generic_to_shared(rs4);
#pragma unroll
        for (int k = 0; k < 4; k++) {
            int idx = tid + 1024 * k;            // 0..4095
            int row = idx >> 7, c4 = idx & 127;
            cp_async16(rs_base + (unsigned)(row * 129 + c4) * 16u,
                       rg4 + (size_t)(nb + row) * 128 + c4);
        }
        asm volatile("cp.async.commit_group;" ::: "memory");
    }

    // ---- y: f32 load -> bf16-hi table + |y|^2 ------------------------------
    const float4* yg4 = (const float4*)y;        // 4096 float4
#pragma unroll
    for (int k = 0; k < 4; k++) {
        int idx  = tid + 1024 * k;
        float4 a = yg4[idx];
        int m = idx >> 3, q = idx & 7;           // pair words 2q, 2q+1
        ybh[m * 20 + 2 * q]     = pack_bf16(a.x, a.y);
        ybh[m * 20 + 2 * q + 1] = pack_bf16(a.z, a.w);
        float sq = fmaf(a.x, a.x, fmaf(a.y, a.y, fmaf(a.z, a.z, a.w * a.w)));
        sq += __shfl_xor_sync(0xffffffffu, sq, 1);
        sq += __shfl_xor_sync(0xffffffffu, sq, 2);
        sq += __shfl_xor_sync(0xffffffffu, sq, 4);
        if (q == 0) yn2[m] = sq;
    }

    // ---- x: hi/lo split for the block's 32 rows + |x|^2 --------------------
    if (tid < 256) {
        int m = tid >> 3, q = tid & 7;
        float4 a = ((const float4*)x)[(nb + m) * 8 + q];
        unsigned h0 = pack_bf16(a.x, a.y), h1 = pack_bf16(a.z, a.w);
        xbh[m * 20 + 2 * q]     = h0;
        xbh[m * 20 + 2 * q + 1] = h1;
        xbl[m * 20 + 2 * q]     = pack_bf16(a.x - bf_lo_f32(h0), a.y - bf_hi_f32(h0));
        xbl[m * 20 + 2 * q + 1] = pack_bf16(a.z - bf_lo_f32(h1), a.w - bf_hi_f32(h1));
        float sq = fmaf(a.x, a.x, fmaf(a.y, a.y, fmaf(a.z, a.z, a.w * a.w)));
        sq += __shfl_xor_sync(0xffffffffu, sq, 1);
        sq += __shfl_xor_sync(0xffffffffu, sq, 2);
        sq += __shfl_xor_sync(0xffffffffu, sq, 4);
        if (q == 0) xn2s[m] = sq;
    }
    __syncthreads();   // tables + norms visible (r still in flight)

    // ---- A fragments: this warp's 16 x-rows, both k-steps, hi and lo -------
    const int la0 = (wr << 4) + g;               // local rows g, g+8 of tile
    const int la1 = la0 + 8;
    unsigned ah[2][4], al[2][4];
#pragma unroll
    for (int ks = 0; ks < 2; ks++) {
        int w0 = t + 8 * ks, w4 = t + 4 + 8 * ks;
        ah[ks][0] = xbh[la0 * 20 + w0];  ah[ks][1] = xbh[la1 * 20 + w0];
        ah[ks][2] = xbh[la0 * 20 + w4];  ah[ks][3] = xbh[la1 * 20 + w4];
        al[ks][0] = xbl[la0 * 20 + w0];  al[ks][1] = xbl[la1 * 20 + w0];
        al[ks][2] = xbl[la0 * 20 + w4];  al[ks][3] = xbl[la1 * 20 + w4];
    }

    // ---- mainloop: 4 n-fragments x 2 k-steps x 2 split terms ---------------
    float acc[4][4];
#pragma unroll
    for (int f = 0; f < 4; f++)
        acc[f][0] = acc[f][1] = acc[f][2] = acc[f][3] = 0.f;

#pragma unroll
    for (int f = 0; f < 4; f++) {
        const int mb = mchunk + 8 * f + g;       // y row this lane feeds
#pragma unroll
        for (int ks = 0; ks < 2; ks++) {
            int w0 = t + 8 * ks, w4 = t + 4 + 8 * ks;
            unsigned bh0 = ybh[mb * 20 + w0], bh1 = ybh[mb * 20 + w4];
            mma_bf16(acc[f][0], acc[f][1], acc[f][2], acc[f][3],
                     ah[ks][0], ah[ks][1], ah[ks][2], ah[ks][3], bh0, bh1);
            mma_bf16(acc[f][0], acc[f][1], acc[f][2], acc[f][3],
                     al[ks][0], al[ks][1], al[ks][2], al[ks][3], bh0, bh1);
        }
    }

    // ---- r landed under the staging + MMA phase ----------------------------
    asm volatile("cp.async.wait_group 0;" ::: "memory");
    __syncthreads();

    // ---- epilogue: rows la0, la1; m-cols mchunk+8f+2t, +1 ------------------
    const float xnA = xn2s[la0], xnB = xn2s[la1];
    float R0 = 0.f, S0 = 0.f, T0 = 0.f, R1 = 0.f, S1 = 0.f, T1 = 0.f;
#pragma unroll
    for (int f = 0; f < 4; f++) {
        const int m0 = mchunk + 8 * f + 2 * t;
        float2 yn = *(const float2*)(yn2 + m0);
        float2 rA = *(const float2*)(sm + RS_OFF + la0 * 516 + m0);
        float2 rB = *(const float2*)(sm + RS_OFF + la1 * 516 + m0);

        float d2, C, K;
        d2 = fmaf(-2.f, acc[f][0], xnA + yn.x);
        C  = sqrt_approx(fmaxf(d2, 0.f)); K = ex2_approx(C * -0.72134752f);
        R0 += K; S0 = fmaf(K, rA.x, S0); T0 = fmaf(K * rA.x, C, T0);

        d2 = fmaf(-2.f, acc[f][1], xnA + yn.y);
        C  = sqrt_approx(fmaxf(d2, 0.f)); K = ex2_approx(C * -0.72134752f);
        R0 += K; S0 = fmaf(K, rA.y, S0); T0 = fmaf(K * rA.y, C, T0);

        d2 = fmaf(-2.f, acc[f][2], xnB + yn.x);
        C  = sqrt_approx(fmaxf(d2, 0.f)); K = ex2_approx(C * -0.72134752f);
        R1 += K; S1 = fmaf(K, rB.x, S1); T1 = fmaf(K * rB.x, C, T1);

        d2 = fmaf(-2.f, acc[f][3], xnB + yn.y);
        C  = sqrt_approx(fmaxf(d2, 0.f)); K = ex2_approx(C * -0.72134752f);
        R1 += K; S1 = fmaf(K, rB.y, S1); T1 = fmaf(K * rB.y, C, T1);
    }

    // reduce across the 4 t-lanes of each g-group
#pragma unroll
    for (int off = 1; off <= 2; off <<= 1) {
        R0 += __shfl_xor_sync(0xffffffffu, R0, off);
        S0 += __shfl_xor_sync(0xffffffffu, S0, off);
        T0 += __shfl_xor_sync(0xffffffffu, T0, off);
        R1 += __shfl_xor_sync(0xffffffffu, R1, off);
        S1 += __shfl_xor_sync(0xffffffffu, S1, off);
        T1 += __shfl_xor_sync(0xffffffffu, T1, off);
    }
    if (t == 0) {
        part[0 * 512 + wc * 32 + la0] = R0;
        part[1 * 512 + wc * 32 + la0] = S0;
        part[2 * 512 + wc * 32 + la0] = T0;
        part[0 * 512 + wc * 32 + la1] = R1;
        part[1 * 512 + wc * 32 + la1] = S1;
        part[2 * 512 + wc * 32 + la1] = T1;
    }
    __syncthreads();

    if (warp == 0) {
        float R = 0.f, S = 0.f, T = 0.f;
#pragma unroll
        for (int w = 0; w < 16; w++) {
            R += part[0 * 512 + w * 32 + lane];
            S += part[1 * 512 + w * 32 + lane];
            T += part[2 * 512 + w * 32 + lane];
        }

        // Scalar Sinkhorn recurrence, block-local early stop:
        //   iter 1:   u = 1/(R + 1e-8)
        //   iter t>1: u = 1/(S/(u+1e-8) + 1e-8)
        //   stop once mean_32 |u_new - u| < 0.1 (after applying update)
        float u = 1.f;
        bool done = false;
        for (int it = 0; it < 100 && !done; it++) {
            float denom = (it == 0) ? R : (S / (u + 1e-8f));
            float un = 1.f / (denom + 1e-8f);
            float e = fabsf(un - u);
            u = un;
#pragma unroll
            for (int off = 16; off > 0; off >>= 1)
                e += __shfl_xor_sync(0xffffffffu, e, off);
            done = (e < 0.1f * 32.f);            // uniform across warp
        }
        out[nb + lane] = u * T / (u + 1e-8f);
    }
}

extern "C" void kernel_launch(void* const* d_in, const int* in_sizes, int n_in,
                              void* d_out, int out_size)
{
    const float* x = (const float*)d_in[0];  // [4096, 32]
    const float* y = (const float*)d_in[1];  // [512, 32]
    const float* r = (const float*)d_in[2];  // [4096, 512]
    float* out = (float*)d_out;              // [4096]

    cudaFuncSetAttribute(sinkhorn_tc_kernel,
                         cudaFuncAttributeMaxDynamicSharedMemorySize, SMEM_BYTES);
    sinkhorn_tc_kernel<<<NBLK, NT, SMEM_BYTES>>>(x, y, r, out);
}